// round 8
// baseline (speedup 1.0000x reference)
#include <cuda_runtime.h>
#include <math.h>
#include <stdint.h>

#define KCMAX 95
#define NUM_DET 100
#define SCORE_THRESH 0.05f
#define NMS_THRESH 0.5f
#define MIN_SIZE 1.0f
#define BBOX_CLIP 4.135166556742356f
#define NMS_THREADS 256
#define CAP 2048                 // processed-candidate cap (expected ~1100)
#define NBKT 64
#define BCAP 256
#define NBINS 576                // score-bit histogram bins
#define HBASE 0x3D4C             // bits(0.05f) >> 16
#define CHUNK_TARGET 224         // per-chunk candidate target (register sort when <=256)
#define SELCAP 512

// ---------------- device scratch ----------------
__device__ float  d_row_max0;
__device__ float  d_row_den0;
__device__ int    d_cnt2[KCMAX][NBKT];        // zeroed at load; NMS resets after use
__device__ float4 d_cand_box[KCMAX][NBKT][BCAP];
__device__ float2 d_cand_sg[KCMAX][NBKT][BCAP];   // score, gi bits

// ---------------- helpers ----------------
__device__ __forceinline__ void decode_box(
    float d0, float d1, float d2, float d3,
    float bx1, float by1, float bx2, float by2,
    float& ox1, float& oy1, float& ox2, float& oy2)
{
    float w  = bx2 - bx1;
    float h  = by2 - by1;
    float cx = bx1 + 0.5f * w;
    float cy = by1 + 0.5f * h;
    float dx = d0 / 10.0f;
    float dy = d1 / 10.0f;
    float dw = fminf(d2 / 5.0f, BBOX_CLIP);
    float dh = fminf(d3 / 5.0f, BBOX_CLIP);
    float pcx = dx * w + cx;
    float pcy = dy * h + cy;
    float pw  = expf(dw) * w;
    float ph  = expf(dh) * h;
    ox1 = pcx - 0.5f * pw;
    oy1 = pcy - 0.5f * ph;
    ox2 = pcx + 0.5f * pw;
    oy2 = pcy + 0.5f * ph;
}

__device__ __forceinline__ float clipf(float v, float hi) {
    return fminf(fmaxf(v, 0.0f), hi);
}

__device__ __forceinline__ unsigned long long u64max(unsigned long long a, unsigned long long b) { return a > b ? a : b; }
__device__ __forceinline__ unsigned long long u64min(unsigned long long a, unsigned long long b) { return a < b ? a : b; }

// ---------------- kernel 1: softmax + decode + filter + bucketed compact ----------------
__global__ __launch_bounds__(256) void score_extract(
    const float* __restrict__ logit,
    const float* __restrict__ breg,
    const float* __restrict__ prop,
    const int* __restrict__ p_ih,
    const int* __restrict__ p_iw,
    int N, int C)
{
    int warp = (blockIdx.x * blockDim.x + threadIdx.x) >> 5;
    int lane = threadIdx.x & 31;
    if (warp >= N) return;

    const float* row = logit + (size_t)warp * C;

    float lv[3];
    float mx = -INFINITY;
#pragma unroll
    for (int j = 0; j < 3; j++) {
        int c = lane + 32 * j;
        lv[j] = (c < C) ? row[c] : -INFINITY;
        mx = fmaxf(mx, lv[j]);
    }
#pragma unroll
    for (int o = 16; o; o >>= 1) mx = fmaxf(mx, __shfl_xor_sync(0xFFFFFFFFu, mx, o));

    float ev[3];
    float s = 0.0f;
#pragma unroll
    for (int j = 0; j < 3; j++) {
        int c = lane + 32 * j;
        ev[j] = (c < C) ? expf(lv[j] - mx) : 0.0f;
        s += ev[j];
    }
#pragma unroll
    for (int o = 16; o; o >>= 1) s += __shfl_xor_sync(0xFFFFFFFFu, s, o);

    if (warp == 0 && lane == 0) { d_row_max0 = mx; d_row_den0 = s; }
    float inv = 1.0f / s;

    float W = (float)(*p_iw);
    float H = (float)(*p_ih);
    float4 p = ((const float4*)prop)[warp];
    int bkt = blockIdx.x & (NBKT - 1);

#pragma unroll
    for (int j = 0; j < 3; j++) {
        int c = lane + 32 * j;
        if (c <= 0 || c >= C) continue;
        float pscore = ev[j] * inv;
        if (pscore >= SCORE_THRESH) {
            const float4 dd = *(const float4*)(breg + ((size_t)warp * C + c) * 4);
            float x1, y1, x2, y2;
            decode_box(dd.x, dd.y, dd.z, dd.w, p.x, p.y, p.z, p.w, x1, y1, x2, y2);
            x1 = clipf(x1, W); x2 = clipf(x2, W);
            y1 = clipf(y1, H); y2 = clipf(y2, H);
            if ((x2 - x1) >= MIN_SIZE && (y2 - y1) >= MIN_SIZE) {
                int cls = c - 1;
                int pos = atomicAdd(&d_cnt2[cls][bkt], 1);
                if (pos < BCAP) {
                    d_cand_box[cls][bkt][pos] = make_float4(x1, y1, x2, y2);
                    d_cand_sg[cls][bkt][pos]  = make_float2(pscore, __int_as_float(warp));
                }
            }
        }
    }
}

// ---------------- kernel 2: incremental-chunk sorted NMS + fused output ----------------
__global__ __launch_bounds__(NMS_THREADS) void nms_out_kernel(
    const float* __restrict__ logit,
    const float* __restrict__ breg,
    const float* __restrict__ treg,
    const float* __restrict__ prop,
    const int* __restrict__ p_ih,
    const int* __restrict__ p_iw,
    float* __restrict__ out,
    int N, int C, int T, int M)
{
    int cls = blockIdx.x;
    int tid = threadIdx.x;
    int laneId = tid & 31;
    int warpId = tid >> 5;

    __shared__ int    s_off[NBKT + 1];
    __shared__ unsigned long long s_key[CAP];     // all keys; fallback sort space
    __shared__ int    hist[NBINS];
    __shared__ unsigned long long s_sel[SELCAP];
    __shared__ float4 s_rbox[SELCAP];
    __shared__ float  s_rarea[SELCAP];
    __shared__ float4 a_box[NUM_DET];
    __shared__ float  a_area[NUM_DET];
    __shared__ int    a_gi[NUM_DET];
    __shared__ float  a_sc[NUM_DET];
    __shared__ int    s_cut, s_chunkn, s_nacc, s_selcnt;

    // ---- bucket prefix (warp 0) ----
    if (warpId == 0) {
        int c0 = min(d_cnt2[cls][2 * laneId],     BCAP);
        int c1 = min(d_cnt2[cls][2 * laneId + 1], BCAP);
        int pair = c0 + c1;
        int incl = pair;
#pragma unroll
        for (int o = 1; o < 32; o <<= 1) {
            int v = __shfl_up_sync(0xFFFFFFFFu, incl, o);
            if (laneId >= o) incl += v;
        }
        s_off[2 * laneId]     = incl - pair;
        s_off[2 * laneId + 1] = incl - c1;
        if (laneId == 31) s_off[NBKT] = incl;
    }
    for (int i = tid; i < NBINS; i += NMS_THREADS) hist[i] = 0;
    if (tid == 0) s_nacc = 0;
    __syncthreads();

    if (tid < NBKT) d_cnt2[cls][tid] = 0;      // reset for next replay
    int cnt = s_off[NBKT];
    if (cnt > CAP) cnt = CAP;

    // ---- bucket-direct key load + histogram (slot packed = bucket<<8 | idx) ----
    for (int b = warpId; b < NBKT; b += (NMS_THREADS >> 5)) {
        int off = s_off[b];
        int c   = s_off[b + 1] - off;
        for (int e = laneId; e < c; e += 32) {
            int i = off + e;
            if (i >= CAP) break;
            float2 sg = d_cand_sg[cls][b][e];
            unsigned u = __float_as_uint(sg.x);                          // score > 0
            unsigned gi_inv = 0xFFFFu - (unsigned)__float_as_int(sg.y);  // N < 65536
            s_key[i] = ((unsigned long long)u << 32) |
                       ((unsigned long long)gi_inv << 16) |
                       (unsigned long long)(unsigned)((b << 8) | e);
            int bin = min((int)(u >> 16) - HBASE, NBINS - 1);
            atomicAdd(&hist[bin], 1);
        }
    }
    __syncthreads();

    // ---- incremental descending-score chunks ----
    // accepted list persists in warp-0 registers across chunks
    float4 rb[4];
    float  ra[4];
#pragma unroll
    for (int s = 0; s < 4; s++) { rb[s] = make_float4(0,0,0,0); ra[s] = 0.0f; }

    int hi_cut = NBINS;        // exclusive upper bin of next chunk
    bool fb = false;
    int ndone = 0;

    while (ndone < NUM_DET && hi_cut > 0 && !fb) {
        // -- warp 0: next cut so that chunk count >= CHUNK_TARGET (or rest) --
        if (warpId == 0) {
            int acc = 0, cut = 0, chn = 0;
            bool found = false;
            int baseStart = ((hi_cut - 1) >> 5) << 5;
            for (int base = baseStart; base >= 0; base -= 32) {
                int bin = base + laneId;
                int v = (bin < hi_cut) ? hist[bin] : 0;
                int tot = v;
#pragma unroll
                for (int o = 16; o; o >>= 1) tot += __shfl_xor_sync(0xFFFFFFFFu, tot, o);
                if (acc + tot >= CHUNK_TARGET) {
                    int suf = v;
#pragma unroll
                    for (int o = 1; o < 32; o <<= 1) {
                        int t = __shfl_down_sync(0xFFFFFFFFu, suf, o);
                        if (laneId + o < 32) suf += t;
                    }
                    unsigned bal = __ballot_sync(0xFFFFFFFFu, acc + suf >= CHUNK_TARGET);
                    int L = 31 - __clz(bal);
                    cut = base + L;
                    chn = acc + __shfl_sync(0xFFFFFFFFu, suf, L);
                    found = true;
                    break;
                }
                acc += tot;
            }
            if (!found) { cut = 0; chn = acc; }
            if (laneId == 0) { s_cut = cut; s_chunkn = chn; s_selcnt = 0; }
        }
        __syncthreads();
        int cutv = s_cut;
        int chn  = s_chunkn;

        if (chn > SELCAP) { fb = true; break; }   // one bin overflows chunk: exact fallback

        if (chn > 0) {
            // -- gather chunk keys: bin in [cutv, hi_cut) --
            for (int i = tid; i < cnt; i += NMS_THREADS) {
                unsigned long long k = s_key[i];
                int bin = min((int)((unsigned)(k >> 32) >> 16) - HBASE, NBINS - 1);
                if (bin >= cutv && bin < hi_cut) {
                    int pos = atomicAdd(&s_selcnt, 1);
                    s_sel[pos] = k;
                }
            }
            __syncthreads();

            if (chn <= NMS_THREADS) {
                // register bitonic 256, descending
                unsigned long long kr = (tid < chn) ? s_sel[tid] : 0ull;
#pragma unroll
                for (int k = 2; k <= NMS_THREADS; k <<= 1) {
#pragma unroll
                    for (int j = k >> 1; j > 0; j >>= 1) {
                        unsigned long long o;
                        if (j >= 32) {
                            s_sel[tid] = kr;
                            __syncthreads();
                            o = s_sel[tid ^ j];
                            __syncthreads();
                        } else {
                            o = __shfl_xor_sync(0xFFFFFFFFu, kr, j);
                        }
                        bool keepMax = ((tid & k) == 0) == ((tid & j) == 0);
                        kr = keepMax ? u64max(kr, o) : u64min(kr, o);
                    }
                }
                s_sel[tid] = kr;
                __syncthreads();
            } else {
                // shared bitonic 512, descending
                for (int i = chn + tid; i < SELCAP; i += NMS_THREADS) s_sel[i] = 0ull;
                __syncthreads();
                for (int k = 2; k <= SELCAP; k <<= 1) {
                    for (int j = k >> 1; j > 0; j >>= 1) {
                        for (int idx = tid; idx < SELCAP; idx += NMS_THREADS) {
                            int l = idx ^ j;
                            if (l > idx) {
                                unsigned long long a = s_sel[idx];
                                unsigned long long b = s_sel[l];
                                bool up = ((idx & k) == 0);
                                if (up ? (a < b) : (a > b)) { s_sel[idx] = b; s_sel[l] = a; }
                            }
                        }
                        __syncthreads();
                    }
                }
            }

            // -- direct box fetch by rank --
            for (int r = tid; r < chn; r += NMS_THREADS) {
                int slot = (int)(s_sel[r] & 0xFFFFu);
                float4 bx = d_cand_box[cls][slot >> 8][slot & 255];
                s_rbox[r]  = bx;
                s_rarea[r] = (bx.z - bx.x) * (bx.w - bx.y);
            }
            __syncthreads();

            // -- warp 0: continue greedy accept over this chunk --
            if (warpId == 0) {
                int nacc = s_nacc;
                for (int i = 0; i < chn && nacc < NUM_DET; i++) {
                    float4 b = s_rbox[i];
                    float carea = s_rarea[i];
                    bool sup = false;
#pragma unroll
                    for (int s = 0; s < 4; s++) {
                        int j = s * 32 + laneId;
                        if (j < nacc) {
                            float ix1 = fmaxf(rb[s].x, b.x);
                            float iy1 = fmaxf(rb[s].y, b.y);
                            float ix2 = fminf(rb[s].z, b.z);
                            float iy2 = fminf(rb[s].w, b.w);
                            float iw = fmaxf(0.0f, ix2 - ix1);
                            float ih = fmaxf(0.0f, iy2 - iy1);
                            float inter = iw * ih;
                            float iou = inter / (ra[s] + carea - inter + 1e-9f);
                            if (iou > NMS_THRESH) sup = true;
                        }
                    }
                    if (!__any_sync(0xFFFFFFFFu, sup)) {
                        if ((nacc & 31) == laneId) {
                            int sl = nacc >> 5;
#pragma unroll
                            for (int s = 0; s < 4; s++) if (sl == s) { rb[s] = b; ra[s] = carea; }
                        }
                        if (laneId == 0) {
                            unsigned long long k = s_sel[i];
                            a_box[nacc] = b;
                            a_gi[nacc]  = (int)(0xFFFFu - ((unsigned)(k >> 16) & 0xFFFFu));
                            a_sc[nacc]  = __uint_as_float((unsigned)(k >> 32));
                        }
                        nacc++;
                    }
                }
                if (laneId == 0) s_nacc = nacc;
            }
            __syncthreads();
        }

        hi_cut = cutv;
        ndone = s_nacc;
        __syncthreads();
    }

    if (fb) {
        // ---- exact fallback (pathological only): full sort + chunked scan ----
        int n2 = 1;
        while (n2 < cnt) n2 <<= 1;
        for (int i = cnt + tid; i < n2; i += NMS_THREADS) s_key[i] = 0ull;
        if (tid == 0) s_nacc = 0;
        __syncthreads();
        for (int k = 2; k <= n2; k <<= 1) {
            for (int j = k >> 1; j > 0; j >>= 1) {
                for (int idx = tid; idx < n2; idx += NMS_THREADS) {
                    int l = idx ^ j;
                    if (l > idx) {
                        unsigned long long a = s_key[idx];
                        unsigned long long b = s_key[l];
                        bool up = ((idx & k) == 0);
                        if (up ? (a < b) : (a > b)) { s_key[idx] = b; s_key[l] = a; }
                    }
                }
                __syncthreads();
            }
        }
        for (int cs = 0; cs < cnt; cs += SELCAP) {
            if (s_nacc >= NUM_DET) break;
            int ce = min(cnt, cs + SELCAP);
            for (int r = cs + tid; r < ce; r += NMS_THREADS) {
                int slot = (int)(s_key[r] & 0xFFFFu);
                float4 bx = d_cand_box[cls][slot >> 8][slot & 255];
                s_rbox[r - cs]  = bx;
                s_rarea[r - cs] = (bx.z - bx.x) * (bx.w - bx.y);
            }
            __syncthreads();
            if (warpId == 0) {
                int nacc = s_nacc;
                for (int i = cs; i < ce && nacc < NUM_DET; i++) {
                    unsigned long long k = s_key[i];
                    float4 b = s_rbox[i - cs];
                    float carea = s_rarea[i - cs];
                    bool sup = false;
#pragma unroll
                    for (int q = 0; q < 4; q++) {
                        int j = laneId + q * 32;
                        if (j < nacc) {
                            float4 a = a_box[j];
                            float ix1 = fmaxf(a.x, b.x);
                            float iy1 = fmaxf(a.y, b.y);
                            float ix2 = fminf(a.z, b.z);
                            float iy2 = fminf(a.w, b.w);
                            float iw = fmaxf(0.0f, ix2 - ix1);
                            float ih = fmaxf(0.0f, iy2 - iy1);
                            float inter = iw * ih;
                            float iou = inter / (a_area[j] + carea - inter + 1e-9f);
                            if (iou > NMS_THRESH) sup = true;
                        }
                    }
                    if (!__any_sync(0xFFFFFFFFu, sup)) {
                        if (laneId == 0) {
                            a_box[nacc]  = b;
                            a_area[nacc] = carea;
                            a_gi[nacc]   = (int)(0xFFFFu - ((unsigned)(k >> 16) & 0xFFFFu));
                            a_sc[nacc]   = __uint_as_float((unsigned)(k >> 32));
                        }
                        nacc++;
                        __syncwarp();
                    }
                }
                if (laneId == 0) s_nacc = nacc;
            }
            __syncthreads();
        }
    }
    __syncthreads();
    int ndet = s_nacc;

    // ---- fused output: 100 detections for this class ----
    float W = (float)(*p_iw);
    float H = (float)(*p_ih);
    int clabel = cls + 1;

    size_t OFF_LBL = (size_t)M * 4;
    size_t OFF_SC  = OFF_LBL + M;
    size_t OFF_FUT = OFF_SC + M;
    size_t OFF_VAL = OFF_FUT + (size_t)T * M * 4;

    for (int d = tid; d < NUM_DET; d += NMS_THREADS) {
        bool v = (d < ndet);
        int g = v ? a_gi[d] : 0;
        int m = cls * NUM_DET + d;

        float4 p = ((const float4*)prop)[g];
        const float4 td0 = *(const float4*)(treg + (((size_t)0 * N + g) * C + clabel) * 4);
        const float4 td1 = *(const float4*)(treg + (((size_t)1 * N + g) * C + clabel) * 4);
        const float4 td2 = *(const float4*)(treg + (((size_t)2 * N + g) * C + clabel) * 4);

        float4 obox;
        float scv;
        if (v) {
            obox = a_box[d];
            scv  = a_sc[d];
        } else {
            // jnp.argmax(all -inf) = 0: emit row-0 data for this class, valid=0
            float lg  = logit[clabel];
            scv = expf(lg - d_row_max0) / d_row_den0;
            const float4 dd = *(const float4*)(breg + (size_t)clabel * 4);
            float x1, y1, x2, y2;
            decode_box(dd.x, dd.y, dd.z, dd.w, p.x, p.y, p.z, p.w, x1, y1, x2, y2);
            obox = make_float4(clipf(x1, W), clipf(y1, H), clipf(x2, W), clipf(y2, H));
        }

        ((float4*)out)[m] = obox;
        out[OFF_LBL + m] = (float)clabel;
        out[OFF_SC + m]  = scv;
        out[OFF_VAL + m] = v ? 1.0f : 0.0f;

        float cx1 = p.x, cy1 = p.y, cx2 = p.z, cy2 = p.w;
        float4 tds[3] = {td0, td1, td2};
#pragma unroll
        for (int t = 0; t < 3; t++) {
            float nx1, ny1, nx2, ny2;
            decode_box(tds[t].x, tds[t].y, tds[t].z, tds[t].w,
                       cx1, cy1, cx2, cy2, nx1, ny1, nx2, ny2);
            float4 of = make_float4(clipf(nx1, W), clipf(ny1, H), clipf(nx2, W), clipf(ny2, H));
            ((float4*)(out + OFF_FUT))[(size_t)t * M + m] = of;
            cx1 = nx1; cy1 = ny1; cx2 = nx2; cy2 = ny2;
        }
    }
}

// ---------------- launch ----------------
extern "C" void kernel_launch(void* const* d_in, const int* in_sizes, int n_in,
                              void* d_out, int out_size)
{
    const float* logit = (const float*)d_in[0];
    const float* breg  = (const float*)d_in[1];
    const float* treg  = (const float*)d_in[2];
    const float* prop  = (const float*)d_in[3];
    const int*   p_ih  = (const int*)d_in[4];
    const int*   p_iw  = (const int*)d_in[5];

    int N = in_sizes[3] / 4;
    int C = in_sizes[0] / N;
    int T = in_sizes[2] / in_sizes[1];
    int KC = C - 1;
    int M = KC * NUM_DET;

    int warpsPerBlock = 8;
    int blocks = (N + warpsPerBlock - 1) / warpsPerBlock;
    score_extract<<<blocks, 256>>>(logit, breg, prop, p_ih, p_iw, N, C);

    nms_out_kernel<<<KC, NMS_THREADS>>>(logit, breg, treg, prop, p_ih, p_iw,
                                        (float*)d_out, N, C, T, M);
}

// round 9
// speedup vs baseline: 1.5293x; 1.5293x over previous
#include <cuda_runtime.h>
#include <math.h>
#include <stdint.h>

#define KCMAX 95
#define NUM_DET 100
#define SCORE_THRESH 0.05f
#define NMS_THRESH 0.5f
#define MIN_SIZE 1.0f
#define BBOX_CLIP 4.135166556742356f
#define NMS_THREADS 256
#define CAP 2048
#define NBKT 64
#define BCAP 256
#define NBINS 576
#define HBASE 0x3D4C             // bits(0.05f) >> 16
#define CHUNK_TARGET 224
#define SELCAP 512

// ---------------- device scratch ----------------
__device__ float  d_row_max0;
__device__ float  d_row_den0;
__device__ int    d_cnt2[KCMAX][NBKT];
__device__ float4 d_cand_box[KCMAX][NBKT][BCAP];
__device__ float2 d_cand_sg[KCMAX][NBKT][BCAP];

// ---------------- helpers ----------------
__device__ __forceinline__ void decode_box(
    float d0, float d1, float d2, float d3,
    float bx1, float by1, float bx2, float by2,
    float& ox1, float& oy1, float& ox2, float& oy2)
{
    float w  = bx2 - bx1;
    float h  = by2 - by1;
    float cx = bx1 + 0.5f * w;
    float cy = by1 + 0.5f * h;
    float dx = d0 / 10.0f;
    float dy = d1 / 10.0f;
    float dw = fminf(d2 / 5.0f, BBOX_CLIP);
    float dh = fminf(d3 / 5.0f, BBOX_CLIP);
    float pcx = dx * w + cx;
    float pcy = dy * h + cy;
    float pw  = expf(dw) * w;
    float ph  = expf(dh) * h;
    ox1 = pcx - 0.5f * pw;
    oy1 = pcy - 0.5f * ph;
    ox2 = pcx + 0.5f * pw;
    oy2 = pcy + 0.5f * ph;
}

__device__ __forceinline__ float clipf(float v, float hi) {
    return fminf(fmaxf(v, 0.0f), hi);
}

__device__ __forceinline__ bool iou_over(const float4& a, float aarea,
                                         const float4& b, float barea)
{
    float ix1 = fmaxf(a.x, b.x);
    float iy1 = fmaxf(a.y, b.y);
    float ix2 = fminf(a.z, b.z);
    float iy2 = fminf(a.w, b.w);
    float iw = fmaxf(0.0f, ix2 - ix1);
    float ih = fmaxf(0.0f, iy2 - iy1);
    float inter = iw * ih;
    float iou = inter / (aarea + barea - inter + 1e-9f);
    return iou > NMS_THRESH;
}

__device__ __forceinline__ unsigned long long u64max(unsigned long long a, unsigned long long b) { return a > b ? a : b; }
__device__ __forceinline__ unsigned long long u64min(unsigned long long a, unsigned long long b) { return a < b ? a : b; }

// ---------------- kernel 1: softmax + decode + filter + bucketed compact ----------------
__global__ __launch_bounds__(256) void score_extract(
    const float* __restrict__ logit,
    const float* __restrict__ breg,
    const float* __restrict__ prop,
    const int* __restrict__ p_ih,
    const int* __restrict__ p_iw,
    int N, int C)
{
    int warp = (blockIdx.x * blockDim.x + threadIdx.x) >> 5;
    int lane = threadIdx.x & 31;
    if (warp >= N) return;

    const float* row = logit + (size_t)warp * C;

    float lv[3];
    float mx = -INFINITY;
#pragma unroll
    for (int j = 0; j < 3; j++) {
        int c = lane + 32 * j;
        lv[j] = (c < C) ? row[c] : -INFINITY;
        mx = fmaxf(mx, lv[j]);
    }
#pragma unroll
    for (int o = 16; o; o >>= 1) mx = fmaxf(mx, __shfl_xor_sync(0xFFFFFFFFu, mx, o));

    float ev[3];
    float s = 0.0f;
#pragma unroll
    for (int j = 0; j < 3; j++) {
        int c = lane + 32 * j;
        ev[j] = (c < C) ? expf(lv[j] - mx) : 0.0f;
        s += ev[j];
    }
#pragma unroll
    for (int o = 16; o; o >>= 1) s += __shfl_xor_sync(0xFFFFFFFFu, s, o);

    if (warp == 0 && lane == 0) { d_row_max0 = mx; d_row_den0 = s; }
    float inv = 1.0f / s;

    float W = (float)(*p_iw);
    float H = (float)(*p_ih);
    float4 p = ((const float4*)prop)[warp];
    int bkt = blockIdx.x & (NBKT - 1);

#pragma unroll
    for (int j = 0; j < 3; j++) {
        int c = lane + 32 * j;
        if (c <= 0 || c >= C) continue;
        float pscore = ev[j] * inv;
        if (pscore >= SCORE_THRESH) {
            const float4 dd = *(const float4*)(breg + ((size_t)warp * C + c) * 4);
            float x1, y1, x2, y2;
            decode_box(dd.x, dd.y, dd.z, dd.w, p.x, p.y, p.z, p.w, x1, y1, x2, y2);
            x1 = clipf(x1, W); x2 = clipf(x2, W);
            y1 = clipf(y1, H); y2 = clipf(y2, H);
            if ((x2 - x1) >= MIN_SIZE && (y2 - y1) >= MIN_SIZE) {
                int cls = c - 1;
                int pos = atomicAdd(&d_cnt2[cls][bkt], 1);
                if (pos < BCAP) {
                    d_cand_box[cls][bkt][pos] = make_float4(x1, y1, x2, y2);
                    d_cand_sg[cls][bkt][pos]  = make_float2(pscore, __int_as_float(warp));
                }
            }
        }
    }
}

// ---------------- kernel 2: chunked NMS w/ warp-tiled parallel accept + fused output ----------------
__global__ __launch_bounds__(NMS_THREADS) void nms_out_kernel(
    const float* __restrict__ logit,
    const float* __restrict__ breg,
    const float* __restrict__ treg,
    const float* __restrict__ prop,
    const int* __restrict__ p_ih,
    const int* __restrict__ p_iw,
    float* __restrict__ out,
    int N, int C, int T, int M)
{
    int cls = blockIdx.x;
    int tid = threadIdx.x;
    int laneId = tid & 31;
    int warpId = tid >> 5;

    __shared__ int    s_off[NBKT + 1];
    __shared__ unsigned long long s_key[CAP];
    __shared__ int    hist[NBINS];
    __shared__ unsigned long long s_sel[SELCAP];
    __shared__ float4 s_rbox[SELCAP];
    __shared__ float  s_rarea[SELCAP];
    __shared__ float4 a_box[NUM_DET];
    __shared__ float  a_area[NUM_DET];
    __shared__ int    a_gi[NUM_DET];
    __shared__ float  a_sc[NUM_DET];
    __shared__ int    s_cut, s_chunkn, s_nacc, s_selcnt;
    __shared__ int    s_sup[8];
    __shared__ int    s_pair[8];

    // ---- bucket prefix (warp 0) ----
    if (warpId == 0) {
        int c0 = min(d_cnt2[cls][2 * laneId],     BCAP);
        int c1 = min(d_cnt2[cls][2 * laneId + 1], BCAP);
        int pair = c0 + c1;
        int incl = pair;
#pragma unroll
        for (int o = 1; o < 32; o <<= 1) {
            int v = __shfl_up_sync(0xFFFFFFFFu, incl, o);
            if (laneId >= o) incl += v;
        }
        s_off[2 * laneId]     = incl - pair;
        s_off[2 * laneId + 1] = incl - c1;
        if (laneId == 31) s_off[NBKT] = incl;
    }
    for (int i = tid; i < NBINS; i += NMS_THREADS) hist[i] = 0;
    if (tid == 0) s_nacc = 0;
    __syncthreads();

    if (tid < NBKT) d_cnt2[cls][tid] = 0;
    int cnt = s_off[NBKT];
    if (cnt > CAP) cnt = CAP;

    // ---- bucket-direct key load + histogram ----
    for (int b = warpId; b < NBKT; b += (NMS_THREADS >> 5)) {
        int off = s_off[b];
        int c   = s_off[b + 1] - off;
        for (int e = laneId; e < c; e += 32) {
            int i = off + e;
            if (i >= CAP) break;
            float2 sg = d_cand_sg[cls][b][e];
            unsigned u = __float_as_uint(sg.x);
            unsigned gi_inv = 0xFFFFu - (unsigned)__float_as_int(sg.y);
            s_key[i] = ((unsigned long long)u << 32) |
                       ((unsigned long long)gi_inv << 16) |
                       (unsigned long long)(unsigned)((b << 8) | e);
            int bin = min((int)(u >> 16) - HBASE, NBINS - 1);
            atomicAdd(&hist[bin], 1);
        }
    }
    __syncthreads();

    // ---- incremental descending-score chunks, warp-tiled accept ----
    float4 rb[4];              // per-warp replicas of accepted boxes
    float  ra[4];
#pragma unroll
    for (int s = 0; s < 4; s++) { rb[s] = make_float4(0,0,0,0); ra[s] = 0.0f; }
    int naccr = 0;             // replicated accepted count (uniform across threads)

    int hi_cut = NBINS;
    bool fb = false;

    while (naccr < NUM_DET && hi_cut > 0 && !fb) {
        // -- warp 0: next chunk cut --
        if (warpId == 0) {
            int acc = 0, cut = 0, chn = 0;
            bool found = false;
            int baseStart = ((hi_cut - 1) >> 5) << 5;
            for (int base = baseStart; base >= 0; base -= 32) {
                int bin = base + laneId;
                int v = (bin < hi_cut) ? hist[bin] : 0;
                int tot = v;
#pragma unroll
                for (int o = 16; o; o >>= 1) tot += __shfl_xor_sync(0xFFFFFFFFu, tot, o);
                if (acc + tot >= CHUNK_TARGET) {
                    int suf = v;
#pragma unroll
                    for (int o = 1; o < 32; o <<= 1) {
                        int t = __shfl_down_sync(0xFFFFFFFFu, suf, o);
                        if (laneId + o < 32) suf += t;
                    }
                    unsigned bal = __ballot_sync(0xFFFFFFFFu, acc + suf >= CHUNK_TARGET);
                    int L = 31 - __clz(bal);
                    cut = base + L;
                    chn = acc + __shfl_sync(0xFFFFFFFFu, suf, L);
                    found = true;
                    break;
                }
                acc += tot;
            }
            if (!found) { cut = 0; chn = acc; }
            if (laneId == 0) { s_cut = cut; s_chunkn = chn; s_selcnt = 0; }
        }
        __syncthreads();
        int cutv = s_cut;
        int chn  = s_chunkn;

        if (chn > SELCAP) { fb = true; break; }

        if (chn > 0) {
            // -- gather chunk keys --
            for (int i = tid; i < cnt; i += NMS_THREADS) {
                unsigned long long k = s_key[i];
                int bin = min((int)((unsigned)(k >> 32) >> 16) - HBASE, NBINS - 1);
                if (bin >= cutv && bin < hi_cut) {
                    int pos = atomicAdd(&s_selcnt, 1);
                    s_sel[pos] = k;
                }
            }
            __syncthreads();

            if (chn <= NMS_THREADS) {
                // register bitonic 256, descending
                unsigned long long kr = (tid < chn) ? s_sel[tid] : 0ull;
#pragma unroll
                for (int k = 2; k <= NMS_THREADS; k <<= 1) {
#pragma unroll
                    for (int j = k >> 1; j > 0; j >>= 1) {
                        unsigned long long o;
                        if (j >= 32) {
                            s_sel[tid] = kr;
                            __syncthreads();
                            o = s_sel[tid ^ j];
                            __syncthreads();
                        } else {
                            o = __shfl_xor_sync(0xFFFFFFFFu, kr, j);
                        }
                        bool keepMax = ((tid & k) == 0) == ((tid & j) == 0);
                        kr = keepMax ? u64max(kr, o) : u64min(kr, o);
                    }
                }
                s_sel[tid] = kr;
                __syncthreads();
            } else {
                for (int i = chn + tid; i < SELCAP; i += NMS_THREADS) s_sel[i] = 0ull;
                __syncthreads();
                for (int k = 2; k <= SELCAP; k <<= 1) {
                    for (int j = k >> 1; j > 0; j >>= 1) {
                        for (int idx = tid; idx < SELCAP; idx += NMS_THREADS) {
                            int l = idx ^ j;
                            if (l > idx) {
                                unsigned long long a = s_sel[idx];
                                unsigned long long b = s_sel[l];
                                bool up = ((idx & k) == 0);
                                if (up ? (a < b) : (a > b)) { s_sel[idx] = b; s_sel[l] = a; }
                            }
                        }
                        __syncthreads();
                    }
                }
            }

            // -- box fetch by rank --
            for (int r = tid; r < chn; r += NMS_THREADS) {
                int slot = (int)(s_sel[r] & 0xFFFFu);
                float4 bx = d_cand_box[cls][slot >> 8][slot & 255];
                s_rbox[r]  = bx;
                s_rarea[r] = (bx.z - bx.x) * (bx.w - bx.y);
            }
            __syncthreads();

            // -- warp-tiled greedy accept: 8 candidates per tile, one per warp --
            for (int tb = 0; tb < chn && naccr < NUM_DET; tb += 8) {
                int i = tb + warpId;
                bool active = (i < chn);
                float4 b = make_float4(0,0,0,0);
                float carea = 0.0f;
                bool sup = false;
                bool pairhit = false;
                if (active) {
                    b = s_rbox[i];
                    carea = s_rarea[i];
                    // vs accepted prefix (register replicas)
#pragma unroll
                    for (int s = 0; s < 4; s++) {
                        int j = s * 32 + laneId;
                        if (j < naccr && iou_over(rb[s], ra[s], b, carea)) sup = true;
                    }
                    // vs earlier tile-mates (lane v tests candidate tb+v, v < warpId)
                    if (laneId < warpId) {
                        float4 bv = s_rbox[tb + laneId];
                        float av = s_rarea[tb + laneId];
                        if (iou_over(bv, av, b, carea)) pairhit = true;
                    }
                }
                bool supacc = __any_sync(0xFFFFFFFFu, sup);
                unsigned pairmask = __ballot_sync(0xFFFFFFFFu, pairhit) & 0xFFu;
                if (laneId == 0) { s_sup[warpId] = supacc ? 1 : 0; s_pair[warpId] = (int)pairmask; }
                __syncthreads();

                // redundant serial resolve (identical in every thread)
                int kept = 0;
                int newn = 0;
#pragma unroll
                for (int w = 0; w < 8; w++) {
                    if (tb + w < chn && naccr + newn < NUM_DET) {
                        bool kk = (s_sup[w] == 0) && ((s_pair[w] & kept) == 0);
                        if (kk) { kept |= (1 << w); newn++; }
                    }
                }

                // append accepted (warp 0, lanes 0-7)
                if (warpId == 0 && laneId < 8 && ((kept >> laneId) & 1)) {
                    int pos = naccr + __popc(kept & ((1 << laneId) - 1));
                    int i2 = tb + laneId;
                    unsigned long long k = s_sel[i2];
                    a_box[pos]  = s_rbox[i2];
                    a_area[pos] = s_rarea[i2];
                    a_gi[pos]   = (int)(0xFFFFu - ((unsigned)(k >> 16) & 0xFFFFu));
                    a_sc[pos]   = __uint_as_float((unsigned)(k >> 32));
                }
                __syncthreads();

                // refresh replicas with newly accepted boxes
                for (int j = naccr; j < naccr + newn; j++) {
                    if ((j & 31) == laneId) {
                        int sl = j >> 5;
                        float4 bb = a_box[j];
                        float  aa = a_area[j];
#pragma unroll
                        for (int q = 0; q < 4; q++) if (q == sl) { rb[q] = bb; ra[q] = aa; }
                    }
                }
                naccr += newn;
            }
            if (tid == 0) s_nacc = naccr;
            __syncthreads();
        }

        hi_cut = cutv;
        __syncthreads();
    }

    if (fb) {
        // ---- exact fallback (pathological only): full sort + chunked serial scan ----
        int n2 = 1;
        while (n2 < cnt) n2 <<= 1;
        for (int i = cnt + tid; i < n2; i += NMS_THREADS) s_key[i] = 0ull;
        if (tid == 0) s_nacc = 0;
        __syncthreads();
        for (int k = 2; k <= n2; k <<= 1) {
            for (int j = k >> 1; j > 0; j >>= 1) {
                for (int idx = tid; idx < n2; idx += NMS_THREADS) {
                    int l = idx ^ j;
                    if (l > idx) {
                        unsigned long long a = s_key[idx];
                        unsigned long long b = s_key[l];
                        bool up = ((idx & k) == 0);
                        if (up ? (a < b) : (a > b)) { s_key[idx] = b; s_key[l] = a; }
                    }
                }
                __syncthreads();
            }
        }
        for (int cs = 0; cs < cnt; cs += SELCAP) {
            if (s_nacc >= NUM_DET) break;
            int ce = min(cnt, cs + SELCAP);
            for (int r = cs + tid; r < ce; r += NMS_THREADS) {
                int slot = (int)(s_key[r] & 0xFFFFu);
                float4 bx = d_cand_box[cls][slot >> 8][slot & 255];
                s_rbox[r - cs]  = bx;
                s_rarea[r - cs] = (bx.z - bx.x) * (bx.w - bx.y);
            }
            __syncthreads();
            if (warpId == 0) {
                int nacc = s_nacc;
                for (int i = cs; i < ce && nacc < NUM_DET; i++) {
                    unsigned long long k = s_key[i];
                    float4 b = s_rbox[i - cs];
                    float carea = s_rarea[i - cs];
                    bool sup = false;
#pragma unroll
                    for (int q = 0; q < 4; q++) {
                        int j = laneId + q * 32;
                        if (j < nacc && iou_over(a_box[j], a_area[j], b, carea)) sup = true;
                    }
                    if (!__any_sync(0xFFFFFFFFu, sup)) {
                        if (laneId == 0) {
                            a_box[nacc]  = b;
                            a_area[nacc] = carea;
                            a_gi[nacc]   = (int)(0xFFFFu - ((unsigned)(k >> 16) & 0xFFFFu));
                            a_sc[nacc]   = __uint_as_float((unsigned)(k >> 32));
                        }
                        nacc++;
                        __syncwarp();
                    }
                }
                if (laneId == 0) s_nacc = nacc;
            }
            __syncthreads();
        }
    }
    __syncthreads();
    int ndet = s_nacc;

    // ---- fused output ----
    float W = (float)(*p_iw);
    float H = (float)(*p_ih);
    int clabel = cls + 1;

    size_t OFF_LBL = (size_t)M * 4;
    size_t OFF_SC  = OFF_LBL + M;
    size_t OFF_FUT = OFF_SC + M;
    size_t OFF_VAL = OFF_FUT + (size_t)T * M * 4;

    for (int d = tid; d < NUM_DET; d += NMS_THREADS) {
        bool v = (d < ndet);
        int g = v ? a_gi[d] : 0;
        int m = cls * NUM_DET + d;

        float4 p = ((const float4*)prop)[g];
        const float4 td0 = *(const float4*)(treg + (((size_t)0 * N + g) * C + clabel) * 4);
        const float4 td1 = *(const float4*)(treg + (((size_t)1 * N + g) * C + clabel) * 4);
        const float4 td2 = *(const float4*)(treg + (((size_t)2 * N + g) * C + clabel) * 4);

        float4 obox;
        float scv;
        if (v) {
            obox = a_box[d];
            scv  = a_sc[d];
        } else {
            float lg  = logit[clabel];
            scv = expf(lg - d_row_max0) / d_row_den0;
            const float4 dd = *(const float4*)(breg + (size_t)clabel * 4);
            float x1, y1, x2, y2;
            decode_box(dd.x, dd.y, dd.z, dd.w, p.x, p.y, p.z, p.w, x1, y1, x2, y2);
            obox = make_float4(clipf(x1, W), clipf(y1, H), clipf(x2, W), clipf(y2, H));
        }

        ((float4*)out)[m] = obox;
        out[OFF_LBL + m] = (float)clabel;
        out[OFF_SC + m]  = scv;
        out[OFF_VAL + m] = v ? 1.0f : 0.0f;

        float cx1 = p.x, cy1 = p.y, cx2 = p.z, cy2 = p.w;
        float4 tds[3] = {td0, td1, td2};
#pragma unroll
        for (int t = 0; t < 3; t++) {
            float nx1, ny1, nx2, ny2;
            decode_box(tds[t].x, tds[t].y, tds[t].z, tds[t].w,
                       cx1, cy1, cx2, cy2, nx1, ny1, nx2, ny2);
            float4 of = make_float4(clipf(nx1, W), clipf(ny1, H), clipf(nx2, W), clipf(ny2, H));
            ((float4*)(out + OFF_FUT))[(size_t)t * M + m] = of;
            cx1 = nx1; cy1 = ny1; cx2 = nx2; cy2 = ny2;
        }
    }
}

// ---------------- launch ----------------
extern "C" void kernel_launch(void* const* d_in, const int* in_sizes, int n_in,
                              void* d_out, int out_size)
{
    const float* logit = (const float*)d_in[0];
    const float* breg  = (const float*)d_in[1];
    const float* treg  = (const float*)d_in[2];
    const float* prop  = (const float*)d_in[3];
    const int*   p_ih  = (const int*)d_in[4];
    const int*   p_iw  = (const int*)d_in[5];

    int N = in_sizes[3] / 4;
    int C = in_sizes[0] / N;
    int T = in_sizes[2] / in_sizes[1];
    int KC = C - 1;
    int M = KC * NUM_DET;

    int warpsPerBlock = 8;
    int blocks = (N + warpsPerBlock - 1) / warpsPerBlock;
    score_extract<<<blocks, 256>>>(logit, breg, prop, p_ih, p_iw, N, C);

    nms_out_kernel<<<KC, NMS_THREADS>>>(logit, breg, treg, prop, p_ih, p_iw,
                                        (float*)d_out, N, C, T, M);
}

// round 10
// speedup vs baseline: 1.6321x; 1.0673x over previous
#include <cuda_runtime.h>
#include <math.h>
#include <stdint.h>

#define KCMAX 95
#define NUM_DET 100
#define SCORE_THRESH 0.05f
#define NMS_THRESH 0.5f
#define MIN_SIZE 1.0f
#define BBOX_CLIP 4.135166556742356f
#define NMS_THREADS 256
#define CAP 2048
#define NBKT 64
#define BCAP 256
#define NBINS 576
#define HBASE 0x3D4C             // bits(0.05f) >> 16
#define CHUNK_TARGET 224
#define SELCAP 512
#define SUPBIT 0x10000

// ---------------- device scratch ----------------
__device__ float  d_row_max0;
__device__ float  d_row_den0;
__device__ int    d_cnt2[KCMAX][NBKT];
__device__ float4 d_cand_box[KCMAX][NBKT][BCAP];
__device__ float2 d_cand_sg[KCMAX][NBKT][BCAP];

// ---------------- helpers ----------------
__device__ __forceinline__ void decode_box(
    float d0, float d1, float d2, float d3,
    float bx1, float by1, float bx2, float by2,
    float& ox1, float& oy1, float& ox2, float& oy2)
{
    float w  = bx2 - bx1;
    float h  = by2 - by1;
    float cx = bx1 + 0.5f * w;
    float cy = by1 + 0.5f * h;
    float dx = d0 / 10.0f;
    float dy = d1 / 10.0f;
    float dw = fminf(d2 / 5.0f, BBOX_CLIP);
    float dh = fminf(d3 / 5.0f, BBOX_CLIP);
    float pcx = dx * w + cx;
    float pcy = dy * h + cy;
    float pw  = expf(dw) * w;
    float ph  = expf(dh) * h;
    ox1 = pcx - 0.5f * pw;
    oy1 = pcy - 0.5f * ph;
    ox2 = pcx + 0.5f * pw;
    oy2 = pcy + 0.5f * ph;
}

__device__ __forceinline__ float clipf(float v, float hi) {
    return fminf(fmaxf(v, 0.0f), hi);
}

__device__ __forceinline__ bool iou_over(const float4& a, float aarea,
                                         const float4& b, float barea)
{
    float ix1 = fmaxf(a.x, b.x);
    float iy1 = fmaxf(a.y, b.y);
    float ix2 = fminf(a.z, b.z);
    float iy2 = fminf(a.w, b.w);
    float iw = fmaxf(0.0f, ix2 - ix1);
    float ih = fmaxf(0.0f, iy2 - iy1);
    float inter = iw * ih;
    float iou = inter / (aarea + barea - inter + 1e-9f);
    return iou > NMS_THRESH;
}

__device__ __forceinline__ unsigned long long u64max(unsigned long long a, unsigned long long b) { return a > b ? a : b; }
__device__ __forceinline__ unsigned long long u64min(unsigned long long a, unsigned long long b) { return a < b ? a : b; }

// ---------------- kernel 1: softmax + decode + filter + bucketed compact ----------------
__global__ __launch_bounds__(256) void score_extract(
    const float* __restrict__ logit,
    const float* __restrict__ breg,
    const float* __restrict__ prop,
    const int* __restrict__ p_ih,
    const int* __restrict__ p_iw,
    int N, int C)
{
    int warp = (blockIdx.x * blockDim.x + threadIdx.x) >> 5;
    int lane = threadIdx.x & 31;
    if (warp >= N) return;

    const float* row = logit + (size_t)warp * C;

    float lv[3];
    float mx = -INFINITY;
#pragma unroll
    for (int j = 0; j < 3; j++) {
        int c = lane + 32 * j;
        lv[j] = (c < C) ? row[c] : -INFINITY;
        mx = fmaxf(mx, lv[j]);
    }
#pragma unroll
    for (int o = 16; o; o >>= 1) mx = fmaxf(mx, __shfl_xor_sync(0xFFFFFFFFu, mx, o));

    float ev[3];
    float s = 0.0f;
#pragma unroll
    for (int j = 0; j < 3; j++) {
        int c = lane + 32 * j;
        ev[j] = (c < C) ? expf(lv[j] - mx) : 0.0f;
        s += ev[j];
    }
#pragma unroll
    for (int o = 16; o; o >>= 1) s += __shfl_xor_sync(0xFFFFFFFFu, s, o);

    if (warp == 0 && lane == 0) { d_row_max0 = mx; d_row_den0 = s; }
    float inv = 1.0f / s;

    float W = (float)(*p_iw);
    float H = (float)(*p_ih);
    float4 p = ((const float4*)prop)[warp];
    int bkt = blockIdx.x & (NBKT - 1);

#pragma unroll
    for (int j = 0; j < 3; j++) {
        int c = lane + 32 * j;
        if (c <= 0 || c >= C) continue;
        float pscore = ev[j] * inv;
        if (pscore >= SCORE_THRESH) {
            const float4 dd = *(const float4*)(breg + ((size_t)warp * C + c) * 4);
            float x1, y1, x2, y2;
            decode_box(dd.x, dd.y, dd.z, dd.w, p.x, p.y, p.z, p.w, x1, y1, x2, y2);
            x1 = clipf(x1, W); x2 = clipf(x2, W);
            y1 = clipf(y1, H); y2 = clipf(y2, H);
            if ((x2 - x1) >= MIN_SIZE && (y2 - y1) >= MIN_SIZE) {
                int cls = c - 1;
                int pos = atomicAdd(&d_cnt2[cls][bkt], 1);
                if (pos < BCAP) {
                    d_cand_box[cls][bkt][pos] = make_float4(x1, y1, x2, y2);
                    d_cand_sg[cls][bkt][pos]  = make_float2(pscore, __int_as_float(warp));
                }
            }
        }
    }
}

// ---------------- kernel 2: chunked NMS, 16-wide single-barrier tiles + fused output ----------------
__global__ __launch_bounds__(NMS_THREADS) void nms_out_kernel(
    const float* __restrict__ logit,
    const float* __restrict__ breg,
    const float* __restrict__ treg,
    const float* __restrict__ prop,
    const int* __restrict__ p_ih,
    const int* __restrict__ p_iw,
    float* __restrict__ out,
    int N, int C, int T, int M)
{
    int cls = blockIdx.x;
    int tid = threadIdx.x;
    int laneId = tid & 31;
    int warpId = tid >> 5;

    __shared__ int    s_off[NBKT + 1];
    __shared__ unsigned long long s_key[CAP];
    __shared__ int    hist[NBINS];
    __shared__ unsigned long long s_sel[SELCAP];
    __shared__ float4 s_rbox[SELCAP];
    __shared__ float  s_rarea[SELCAP];
    __shared__ float4 a_box[NUM_DET];
    __shared__ float  a_area[NUM_DET];
    __shared__ int    a_gi[NUM_DET];
    __shared__ float  a_sc[NUM_DET];
    __shared__ int    s_cut, s_chunkn, s_nacc, s_selcnt;
    __shared__ int    s_pairm[2][16];     // double-buffered pair/sup masks

    // ---- bucket prefix (warp 0) ----
    if (warpId == 0) {
        int c0 = min(d_cnt2[cls][2 * laneId],     BCAP);
        int c1 = min(d_cnt2[cls][2 * laneId + 1], BCAP);
        int pair = c0 + c1;
        int incl = pair;
#pragma unroll
        for (int o = 1; o < 32; o <<= 1) {
            int v = __shfl_up_sync(0xFFFFFFFFu, incl, o);
            if (laneId >= o) incl += v;
        }
        s_off[2 * laneId]     = incl - pair;
        s_off[2 * laneId + 1] = incl - c1;
        if (laneId == 31) s_off[NBKT] = incl;
    }
    for (int i = tid; i < NBINS; i += NMS_THREADS) hist[i] = 0;
    if (tid == 0) s_nacc = 0;
    __syncthreads();

    if (tid < NBKT) d_cnt2[cls][tid] = 0;
    int cnt = s_off[NBKT];
    if (cnt > CAP) cnt = CAP;

    // ---- bucket-direct key load + histogram ----
    for (int b = warpId; b < NBKT; b += (NMS_THREADS >> 5)) {
        int off = s_off[b];
        int c   = s_off[b + 1] - off;
        for (int e = laneId; e < c; e += 32) {
            int i = off + e;
            if (i >= CAP) break;
            float2 sg = d_cand_sg[cls][b][e];
            unsigned u = __float_as_uint(sg.x);
            unsigned gi_inv = 0xFFFFu - (unsigned)__float_as_int(sg.y);
            s_key[i] = ((unsigned long long)u << 32) |
                       ((unsigned long long)gi_inv << 16) |
                       (unsigned long long)(unsigned)((b << 8) | e);
            int bin = min((int)(u >> 16) - HBASE, NBINS - 1);
            atomicAdd(&hist[bin], 1);
        }
    }
    __syncthreads();

    // ---- incremental descending-score chunks ----
    float4 rb[4];              // per-warp replicas of accepted boxes
    float  ra[4];
#pragma unroll
    for (int s = 0; s < 4; s++) { rb[s] = make_float4(0,0,0,0); ra[s] = 0.0f; }
    int naccr = 0;

    int hi_cut = NBINS;
    bool fb = false;

    while (naccr < NUM_DET && hi_cut > 0 && !fb) {
        // -- warp 0: next chunk cut --
        if (warpId == 0) {
            int acc = 0, cut = 0, chn = 0;
            bool found = false;
            int baseStart = ((hi_cut - 1) >> 5) << 5;
            for (int base = baseStart; base >= 0; base -= 32) {
                int bin = base + laneId;
                int v = (bin < hi_cut) ? hist[bin] : 0;
                int tot = v;
#pragma unroll
                for (int o = 16; o; o >>= 1) tot += __shfl_xor_sync(0xFFFFFFFFu, tot, o);
                if (acc + tot >= CHUNK_TARGET) {
                    int suf = v;
#pragma unroll
                    for (int o = 1; o < 32; o <<= 1) {
                        int t = __shfl_down_sync(0xFFFFFFFFu, suf, o);
                        if (laneId + o < 32) suf += t;
                    }
                    unsigned bal = __ballot_sync(0xFFFFFFFFu, acc + suf >= CHUNK_TARGET);
                    int L = 31 - __clz(bal);
                    cut = base + L;
                    chn = acc + __shfl_sync(0xFFFFFFFFu, suf, L);
                    found = true;
                    break;
                }
                acc += tot;
            }
            if (!found) { cut = 0; chn = acc; }
            if (laneId == 0) { s_cut = cut; s_chunkn = chn; s_selcnt = 0; }
        }
        __syncthreads();
        int cutv = s_cut;
        int chn  = s_chunkn;

        if (chn > SELCAP) { fb = true; break; }

        if (chn > 0) {
            // -- gather chunk keys --
            for (int i = tid; i < cnt; i += NMS_THREADS) {
                unsigned long long k = s_key[i];
                int bin = min((int)((unsigned)(k >> 32) >> 16) - HBASE, NBINS - 1);
                if (bin >= cutv && bin < hi_cut) {
                    int pos = atomicAdd(&s_selcnt, 1);
                    s_sel[pos] = k;
                }
            }
            __syncthreads();

            if (chn <= NMS_THREADS) {
                // register bitonic 256, descending
                unsigned long long kr = (tid < chn) ? s_sel[tid] : 0ull;
#pragma unroll
                for (int k = 2; k <= NMS_THREADS; k <<= 1) {
#pragma unroll
                    for (int j = k >> 1; j > 0; j >>= 1) {
                        unsigned long long o;
                        if (j >= 32) {
                            s_sel[tid] = kr;
                            __syncthreads();
                            o = s_sel[tid ^ j];
                            __syncthreads();
                        } else {
                            o = __shfl_xor_sync(0xFFFFFFFFu, kr, j);
                        }
                        bool keepMax = ((tid & k) == 0) == ((tid & j) == 0);
                        kr = keepMax ? u64max(kr, o) : u64min(kr, o);
                    }
                }
                s_sel[tid] = kr;
                __syncthreads();
            } else {
                for (int i = chn + tid; i < SELCAP; i += NMS_THREADS) s_sel[i] = 0ull;
                __syncthreads();
                for (int k = 2; k <= SELCAP; k <<= 1) {
                    for (int j = k >> 1; j > 0; j >>= 1) {
                        for (int idx = tid; idx < SELCAP; idx += NMS_THREADS) {
                            int l = idx ^ j;
                            if (l > idx) {
                                unsigned long long a = s_sel[idx];
                                unsigned long long b = s_sel[l];
                                bool up = ((idx & k) == 0);
                                if (up ? (a < b) : (a > b)) { s_sel[idx] = b; s_sel[l] = a; }
                            }
                        }
                        __syncthreads();
                    }
                }
            }

            // -- box fetch by rank --
            for (int r = tid; r < chn; r += NMS_THREADS) {
                int slot = (int)(s_sel[r] & 0xFFFFu);
                float4 bx = d_cand_box[cls][slot >> 8][slot & 255];
                s_rbox[r]  = bx;
                s_rarea[r] = (bx.z - bx.x) * (bx.w - bx.y);
            }
            __syncthreads();

            // -- 16-wide single-barrier tiles: warp w owns candidates tb+w, tb+8+w --
            for (int tb = 0; tb < chn && naccr < NUM_DET; tb += 16) {
                int buf = (tb >> 4) & 1;
                int i1 = tb + warpId;
                int i2 = tb + 8 + warpId;

                bool sup1 = false, pair1 = false;
                bool sup2 = false, pair2 = false;
                if (i1 < chn) {
                    float4 b1 = s_rbox[i1];
                    float ca1 = s_rarea[i1];
#pragma unroll
                    for (int s = 0; s < 4; s++) {
                        int j = s * 32 + laneId;
                        if (j < naccr && iou_over(rb[s], ra[s], b1, ca1)) sup1 = true;
                    }
                    if (laneId < warpId)
                        pair1 = iou_over(s_rbox[tb + laneId], s_rarea[tb + laneId], b1, ca1);
                }
                if (i2 < chn) {
                    float4 b2 = s_rbox[i2];
                    float ca2 = s_rarea[i2];
#pragma unroll
                    for (int s = 0; s < 4; s++) {
                        int j = s * 32 + laneId;
                        if (j < naccr && iou_over(rb[s], ra[s], b2, ca2)) sup2 = true;
                    }
                    if (laneId < 8 + warpId)
                        pair2 = iou_over(s_rbox[tb + laneId], s_rarea[tb + laneId], b2, ca2);
                }
                unsigned bal1 = __ballot_sync(0xFFFFFFFFu, pair1) & ((1u << warpId) - 1u);
                unsigned bal2 = __ballot_sync(0xFFFFFFFFu, pair2) & ((1u << (8 + warpId)) - 1u);
                bool s1 = __any_sync(0xFFFFFFFFu, sup1);
                bool s2 = __any_sync(0xFFFFFFFFu, sup2);
                if (laneId == 0) {
                    s_pairm[buf][warpId]     = (int)bal1 | (s1 ? SUPBIT : 0);
                    s_pairm[buf][8 + warpId] = (int)bal2 | (s2 ? SUPBIT : 0);
                }
                __syncthreads();       // the only barrier in the tile

                // redundant resolve (identical in every thread)
                int kept = 0, newn = 0;
#pragma unroll
                for (int t = 0; t < 16; t++) {
                    if (tb + t < chn && naccr + newn < NUM_DET) {
                        int pm = s_pairm[buf][t];
                        if (!(pm & SUPBIT) && !(pm & kept)) { kept |= 1 << t; newn++; }
                    }
                }

                // append accepted (warp 0, lanes 0-15); consumed only after final sync
                if (warpId == 0 && laneId < 16 && ((kept >> laneId) & 1)) {
                    int pos = naccr + __popc(kept & ((1 << laneId) - 1));
                    int ii = tb + laneId;
                    unsigned long long k = s_sel[ii];
                    a_box[pos]  = s_rbox[ii];
                    a_area[pos] = s_rarea[ii];
                    a_gi[pos]   = (int)(0xFFFFu - ((unsigned)(k >> 16) & 0xFFFFu));
                    a_sc[pos]   = __uint_as_float((unsigned)(k >> 32));
                }

                // self-refresh replicas straight from s_rbox (no barrier needed)
                int rank = 0;
#pragma unroll
                for (int t = 0; t < 16; t++) {
                    if ((kept >> t) & 1) {
                        int pos = naccr + rank;
                        if ((pos & 31) == laneId) {
                            int sl = pos >> 5;
                            float4 bb = s_rbox[tb + t];
                            float  aa = s_rarea[tb + t];
#pragma unroll
                            for (int q = 0; q < 4; q++) if (q == sl) { rb[q] = bb; ra[q] = aa; }
                        }
                        rank++;
                    }
                }
                naccr += newn;
            }
            if (tid == 0) s_nacc = naccr;
            __syncthreads();
        }

        hi_cut = cutv;
        __syncthreads();
    }

    if (fb) {
        // ---- exact fallback (pathological only): full sort + chunked serial scan ----
        int n2 = 1;
        while (n2 < cnt) n2 <<= 1;
        for (int i = cnt + tid; i < n2; i += NMS_THREADS) s_key[i] = 0ull;
        if (tid == 0) s_nacc = 0;
        __syncthreads();
        for (int k = 2; k <= n2; k <<= 1) {
            for (int j = k >> 1; j > 0; j >>= 1) {
                for (int idx = tid; idx < n2; idx += NMS_THREADS) {
                    int l = idx ^ j;
                    if (l > idx) {
                        unsigned long long a = s_key[idx];
                        unsigned long long b = s_key[l];
                        bool up = ((idx & k) == 0);
                        if (up ? (a < b) : (a > b)) { s_key[idx] = b; s_key[l] = a; }
                    }
                }
                __syncthreads();
            }
        }
        for (int cs = 0; cs < cnt; cs += SELCAP) {
            if (s_nacc >= NUM_DET) break;
            int ce = min(cnt, cs + SELCAP);
            for (int r = cs + tid; r < ce; r += NMS_THREADS) {
                int slot = (int)(s_key[r] & 0xFFFFu);
                float4 bx = d_cand_box[cls][slot >> 8][slot & 255];
                s_rbox[r - cs]  = bx;
                s_rarea[r - cs] = (bx.z - bx.x) * (bx.w - bx.y);
            }
            __syncthreads();
            if (warpId == 0) {
                int nacc = s_nacc;
                for (int i = cs; i < ce && nacc < NUM_DET; i++) {
                    unsigned long long k = s_key[i];
                    float4 b = s_rbox[i - cs];
                    float carea = s_rarea[i - cs];
                    bool sup = false;
#pragma unroll
                    for (int q = 0; q < 4; q++) {
                        int j = laneId + q * 32;
                        if (j < nacc && iou_over(a_box[j], a_area[j], b, carea)) sup = true;
                    }
                    if (!__any_sync(0xFFFFFFFFu, sup)) {
                        if (laneId == 0) {
                            a_box[nacc]  = b;
                            a_area[nacc] = carea;
                            a_gi[nacc]   = (int)(0xFFFFu - ((unsigned)(k >> 16) & 0xFFFFu));
                            a_sc[nacc]   = __uint_as_float((unsigned)(k >> 32));
                        }
                        nacc++;
                        __syncwarp();
                    }
                }
                if (laneId == 0) s_nacc = nacc;
            }
            __syncthreads();
        }
    }
    __syncthreads();
    int ndet = s_nacc;

    // ---- fused output ----
    float W = (float)(*p_iw);
    float H = (float)(*p_ih);
    int clabel = cls + 1;

    size_t OFF_LBL = (size_t)M * 4;
    size_t OFF_SC  = OFF_LBL + M;
    size_t OFF_FUT = OFF_SC + M;
    size_t OFF_VAL = OFF_FUT + (size_t)T * M * 4;

    for (int d = tid; d < NUM_DET; d += NMS_THREADS) {
        bool v = (d < ndet);
        int g = v ? a_gi[d] : 0;
        int m = cls * NUM_DET + d;

        float4 p = ((const float4*)prop)[g];
        const float4 td0 = *(const float4*)(treg + (((size_t)0 * N + g) * C + clabel) * 4);
        const float4 td1 = *(const float4*)(treg + (((size_t)1 * N + g) * C + clabel) * 4);
        const float4 td2 = *(const float4*)(treg + (((size_t)2 * N + g) * C + clabel) * 4);

        float4 obox;
        float scv;
        if (v) {
            obox = a_box[d];
            scv  = a_sc[d];
        } else {
            float lg  = logit[clabel];
            scv = expf(lg - d_row_max0) / d_row_den0;
            const float4 dd = *(const float4*)(breg + (size_t)clabel * 4);
            float x1, y1, x2, y2;
            decode_box(dd.x, dd.y, dd.z, dd.w, p.x, p.y, p.z, p.w, x1, y1, x2, y2);
            obox = make_float4(clipf(x1, W), clipf(y1, H), clipf(x2, W), clipf(y2, H));
        }

        ((float4*)out)[m] = obox;
        out[OFF_LBL + m] = (float)clabel;
        out[OFF_SC + m]  = scv;
        out[OFF_VAL + m] = v ? 1.0f : 0.0f;

        float cx1 = p.x, cy1 = p.y, cx2 = p.z, cy2 = p.w;
        float4 tds[3] = {td0, td1, td2};
#pragma unroll
        for (int t = 0; t < 3; t++) {
            float nx1, ny1, nx2, ny2;
            decode_box(tds[t].x, tds[t].y, tds[t].z, tds[t].w,
                       cx1, cy1, cx2, cy2, nx1, ny1, nx2, ny2);
            float4 of = make_float4(clipf(nx1, W), clipf(ny1, H), clipf(nx2, W), clipf(ny2, H));
            ((float4*)(out + OFF_FUT))[(size_t)t * M + m] = of;
            cx1 = nx1; cy1 = ny1; cx2 = nx2; cy2 = ny2;
        }
    }
}

// ---------------- launch ----------------
extern "C" void kernel_launch(void* const* d_in, const int* in_sizes, int n_in,
                              void* d_out, int out_size)
{
    const float* logit = (const float*)d_in[0];
    const float* breg  = (const float*)d_in[1];
    const float* treg  = (const float*)d_in[2];
    const float* prop  = (const float*)d_in[3];
    const int*   p_ih  = (const int*)d_in[4];
    const int*   p_iw  = (const int*)d_in[5];

    int N = in_sizes[3] / 4;
    int C = in_sizes[0] / N;
    int T = in_sizes[2] / in_sizes[1];
    int KC = C - 1;
    int M = KC * NUM_DET;

    int warpsPerBlock = 8;
    int blocks = (N + warpsPerBlock - 1) / warpsPerBlock;
    score_extract<<<blocks, 256>>>(logit, breg, prop, p_ih, p_iw, N, C);

    nms_out_kernel<<<KC, NMS_THREADS>>>(logit, breg, treg, prop, p_ih, p_iw,
                                        (float*)d_out, N, C, T, M);
}